// round 13
// baseline (speedup 1.0000x reference)
#include <cuda_runtime.h>
#include <cuda_fp16.h>
#include <cstdint>

#define N_NODES 400000
#define N_EDGES 400000
#define N_PAD   400128   // 1563 * 256-row tiles
#define NPB 50000

// ---------------- scratch (device globals: no allocation allowed) ----------
__device__ float g_dis[N_PAD];                     // zero-init padding => t=0 there
__device__ int   g_deg[N_NODES];
__device__ int   g_src[N_EDGES];
__device__ int   g_dst[N_EDGES];
__device__ __half g_agg1[(size_t)N_PAD * 64];
__device__ __half g_x16[(size_t)N_NODES * 64];    // x * dis  (pre-scaled)
__device__ __half g_t[(size_t)N_PAD * 64];        // t * dis  (pre-scaled)
__device__ __half g_agg2[(size_t)N_PAD * 64];
__device__ float g_pooled[512];

// ---------------- decode (int32 proven on this dataset) + degree ------------
__global__ void decode_kernel(const int* __restrict__ ei) {
    int e = blockIdx.x * 256 + threadIdx.x;
    if (e >= N_EDGES) return;
    int s = ei[e], d = ei[N_EDGES + e];
    s = min(max(s, 0), N_NODES - 1);    // guard: wrong dtype -> rel_err, not trap
    d = min(max(d, 0), N_NODES - 1);
    g_src[e] = s;
    g_dst[e] = d;
    atomicAdd(&g_deg[d], 1);
}

// ---------------- init: dis + agg1 seed (x*dis^2) + x16 = x*dis -------------
__global__ void init_kernel(const float* __restrict__ x) {
    int gid = blockIdx.x * 256 + threadIdx.x;   // 8 threads/node, 8 floats each
    int i = gid >> 3, q = gid & 7;
    if (i >= N_NODES) return;
    float dv = rsqrtf((float)(g_deg[i] + 1));   // +1 self loop
    if (q == 0) g_dis[i] = dv;
    float dv2 = dv * dv;
    const float4* xp = (const float4*)(x + (size_t)i * 64 + q * 8);
    float4 a = xp[0], b = xp[1];
    uint4 o, s;
    *(__half2*)&o.x = __float22half2_rn(make_float2(a.x * dv, a.y * dv));
    *(__half2*)&o.y = __float22half2_rn(make_float2(a.z * dv, a.w * dv));
    *(__half2*)&o.z = __float22half2_rn(make_float2(b.x * dv, b.y * dv));
    *(__half2*)&o.w = __float22half2_rn(make_float2(b.z * dv, b.w * dv));
    *(__half2*)&s.x = __float22half2_rn(make_float2(a.x * dv2, a.y * dv2));
    *(__half2*)&s.y = __float22half2_rn(make_float2(a.z * dv2, a.w * dv2));
    *(__half2*)&s.z = __float22half2_rn(make_float2(b.x * dv2, b.y * dv2));
    *(__half2*)&s.w = __float22half2_rn(make_float2(b.z * dv2, b.w * dv2));
    ((uint4*)g_x16)[(size_t)i * 8 + q] = o;
    ((uint4*)g_agg1)[(size_t)i * 8 + q] = s;
}

// ---------------- generic edge scatter: out[d] += F[s] * dis[d] --------------
// (F rows are pre-scaled by dis[src])
__device__ __forceinline__ void red_f16x8(__half* p, uint32_t r0, uint32_t r1,
                                          uint32_t r2, uint32_t r3) {
    asm volatile("red.global.add.noftz.v4.f16x2 [%0], {%1,%2,%3,%4};"
                 :: "l"(p), "r"(r0), "r"(r1), "r"(r2), "r"(r3) : "memory");
}

__device__ __forceinline__ uint32_t pack_h2(float a, float b) {
    __half2 h = __float22half2_rn(make_float2(a, b));
    return *(uint32_t*)&h;
}

__global__ void scatter_kernel(const __half* __restrict__ F,
                               __half* __restrict__ out) {
    int gid = blockIdx.x * 256 + threadIdx.x;
    int e = gid >> 3, q = gid & 7;   // 8 threads/edge, 8 fp16 (16B) each
    if (e >= N_EDGES) return;
    int s = g_src[e], d = g_dst[e];
    float w = g_dis[d];
    uint4 raw = ((const uint4*)(F + (size_t)s * 64))[q];
    float2 f0 = __half22float2(*(__half2*)&raw.x);
    float2 f1 = __half22float2(*(__half2*)&raw.y);
    float2 f2 = __half22float2(*(__half2*)&raw.z);
    float2 f3 = __half22float2(*(__half2*)&raw.w);
    red_f16x8(out + (size_t)d * 64 + q * 8,
              pack_h2(f0.x * w, f0.y * w), pack_h2(f1.x * w, f1.y * w),
              pack_h2(f2.x * w, f2.y * w), pack_h2(f3.x * w, f3.y * w));
}

// ---------------- HMMA + ldmatrix helpers -------------------------------------
__device__ __forceinline__ void mma16816(float* d, const uint32_t* a, const uint32_t* b) {
    asm volatile(
        "mma.sync.aligned.m16n8k16.row.col.f32.f16.f16.f32 "
        "{%0,%1,%2,%3}, {%4,%5,%6,%7}, {%8,%9}, {%0,%1,%2,%3};"
        : "+f"(d[0]), "+f"(d[1]), "+f"(d[2]), "+f"(d[3])
        : "r"(a[0]), "r"(a[1]), "r"(a[2]), "r"(a[3]), "r"(b[0]), "r"(b[1]));
}

__device__ __forceinline__ void ldsm_x4(uint32_t* r, uint32_t addr) {
    asm volatile("ldmatrix.sync.aligned.m8n8.x4.shared.b16 {%0,%1,%2,%3}, [%4];"
                 : "=r"(r[0]), "=r"(r[1]), "=r"(r[2]), "=r"(r[3]) : "r"(addr));
}

__device__ __forceinline__ uint32_t smem_u32(const void* p) {
    uint32_t a;
    asm("{ .reg .u64 t; cvta.to.shared.u64 t, %1; cvt.u32.u64 %0, t; }" : "=r"(a) : "l"(p));
    return a;
}

__device__ __forceinline__ void cp16(uint32_t saddr, const void* g) {
    asm volatile("cp.async.cg.shared.global [%0], [%1], 16;" :: "r"(saddr), "l"(g));
}

// ---------------- fused double GEMM (fp16, 32 rows/warp) ----------------------
// t' = ( relu(agg1 @ W1 + b1) @ W2 ) * dis ; agg2 seed = t * dis^2.
// 256-row tiles, 8 warps, each warp owns two 16-row groups -> every B fragment
// feeds 4 MMAs (2 row groups x 2 n-tiles): B smem traffic per row is HALVED
// vs 16 rows/warp. h1 stays in registers (accumulator fragment == A fragment).
__global__ void __launch_bounds__(256, 1)
fused_gemm_kernel(const __half* __restrict__ X, const float* __restrict__ W1g,
                  const float* __restrict__ b1, const float* __restrict__ W2g,
                  __half* __restrict__ T, __half* __restrict__ Agg,
                  int tiles) {
    constexpr int K1 = 64, H = 128, N2 = 64;
    constexpr int SA1 = K1 + 8;   // 72
    constexpr int SA2 = H + 8;    // 136
    constexpr int NT1 = H / 8;    // 16
    constexpr int KS1 = K1 / 16;  // 4
    constexpr int NT2 = N2 / 8;   // 8
    constexpr int KS2 = H / 16;   // 8
    constexpr int ROWS = 256;     // tile rows

    extern __shared__ __align__(16) char smraw[];
    __half* A0 = (__half*)smraw;          // 256*SA1
    __half* A1 = A0 + ROWS * SA1;
    __half* B1 = A1 + ROWS * SA1;         // H*SA1
    __half* B2 = B1 + H * SA1;            // N2*SA2
    float* sbias = (float*)(B2 + N2 * SA2);   // H floats

    int tid = threadIdx.x, wid = tid >> 5, lane = tid & 31;
    int g = lane >> 2, tg = lane & 3;
    int r0 = wid * 32;                    // warp's 32-row slice

    // W1 [K1 x H] -> B1 [n][k] fp16
    for (int e = tid; e < K1 * H; e += 256) {
        int k = e / H, n = e % H;
        B1[n * SA1 + k] = __float2half_rn(W1g[e]);
    }
    // W2 [H x N2] -> B2 [n][k] fp16
    for (int e = tid; e < H * N2; e += 256) {
        int k = e / N2, n = e % N2;
        B2[n * SA2 + k] = __float2half_rn(W2g[e]);
    }
    for (int j = tid; j < H; j += 256) sbias[j] = b1[j];

    uint32_t sA[2] = { smem_u32(A0), smem_u32(A1) };
    // A ldmatrix.x4 lane addresses for the two 16-row groups
    uint32_t a_row0 = (uint32_t)((lane & 15) + r0) * SA1 * 2 + ((lane >> 4) << 4);
    uint32_t a_row1 = a_row0 + 16 * SA1 * 2;
    // B ldmatrix.x4 lane address: 4 matrices = {nt, nt+1} x {k0, k0+8}
    uint32_t bpr = (uint32_t)((lane & 7) + ((lane >> 4) << 3));   // row within pair
    uint32_t bkh = ((lane >> 3) & 1) << 3;                        // k-half offset
    uint32_t b1_addr = smem_u32(B1) + (bpr * SA1 + bkh) * 2;
    uint32_t b2_addr = smem_u32(B2) + (bpr * SA2 + bkh) * 2;

    {   // prologue: prefetch first tile (256 rows x 128B)
        const char* gp = (const char*)(X + (size_t)blockIdx.x * ROWS * K1);
        #pragma unroll
        for (int j = 0; j < 8; j++) {
            int idx = tid + j * 256;
            int row = idx >> 3, q = idx & 7;
            cp16(sA[0] + row * (SA1 * 2) + q * 16, gp + row * 128 + q * 16);
        }
        asm volatile("cp.async.commit_group;" ::: "memory");
    }

    int it = 0;
    for (int tile = blockIdx.x; tile < tiles; tile += gridDim.x, it++) {
        __syncthreads();
        int nxt = tile + gridDim.x;
        if (nxt < tiles) {
            const char* gp = (const char*)(X + (size_t)nxt * ROWS * K1);
            uint32_t sn = sA[(it + 1) & 1];
            #pragma unroll
            for (int j = 0; j < 8; j++) {
                int idx = tid + j * 256;
                int row = idx >> 3, q = idx & 7;
                cp16(sn + row * (SA1 * 2) + q * 16, gp + row * 128 + q * 16);
            }
            asm volatile("cp.async.commit_group;" ::: "memory");
            asm volatile("cp.async.wait_group 1;" ::: "memory");
        } else {
            asm volatile("cp.async.wait_group 0;" ::: "memory");
        }
        __syncthreads();

        uint32_t aBase0 = sA[it & 1] + a_row0;
        uint32_t aBase1 = sA[it & 1] + a_row1;

        // ---- stage 1: acc1 = A @ W1 (two row groups share each B fragment) ----
        float acc1[2][NT1][4];
        #pragma unroll
        for (int rg = 0; rg < 2; rg++)
            #pragma unroll
            for (int nt = 0; nt < NT1; nt++)
                #pragma unroll
                for (int j = 0; j < 4; j++) acc1[rg][nt][j] = 0.0f;

        #pragma unroll
        for (int ks = 0; ks < KS1; ks++) {
            int k0 = ks * 16;
            uint32_t a0[4], a1[4];
            ldsm_x4(a0, aBase0 + k0 * 2);
            ldsm_x4(a1, aBase1 + k0 * 2);
            #pragma unroll
            for (int ntp = 0; ntp < NT1 / 2; ntp++) {
                uint32_t b[4];
                ldsm_x4(b, b1_addr + (ntp * 16 * SA1 + k0) * 2);
                mma16816(acc1[0][2 * ntp],     a0, b);
                mma16816(acc1[0][2 * ntp + 1], a0, b + 2);
                mma16816(acc1[1][2 * ntp],     a1, b);
                mma16816(acc1[1][2 * ntp + 1], a1, b + 2);
            }
        }

        // ---- bias + relu + pack: h fragments (A-operand layout for stage 2) ----
        uint32_t hw[2][2 * NT1];
        #pragma unroll
        for (int rg = 0; rg < 2; rg++)
            #pragma unroll
            for (int nt = 0; nt < NT1; nt++) {
                int col = nt * 8 + tg * 2;
                float v0 = fmaxf(acc1[rg][nt][0] + sbias[col], 0.0f);
                float v1 = fmaxf(acc1[rg][nt][1] + sbias[col + 1], 0.0f);
                float v2 = fmaxf(acc1[rg][nt][2] + sbias[col], 0.0f);
                float v3 = fmaxf(acc1[rg][nt][3] + sbias[col + 1], 0.0f);
                hw[rg][2 * nt]     = pack_h2(v0, v1);   // row g
                hw[rg][2 * nt + 1] = pack_h2(v2, v3);   // row g+8
            }

        // ---- stage 2: acc2 = h @ W2, h from registers ----
        float acc2[2][NT2][4];
        #pragma unroll
        for (int rg = 0; rg < 2; rg++)
            #pragma unroll
            for (int nt = 0; nt < NT2; nt++)
                #pragma unroll
                for (int j = 0; j < 4; j++) acc2[rg][nt][j] = 0.0f;

        #pragma unroll
        for (int ks = 0; ks < KS2; ks++) {
            int k0 = ks * 16;
            #pragma unroll
            for (int ntp = 0; ntp < NT2 / 2; ntp++) {
                uint32_t b[4];
                ldsm_x4(b, b2_addr + (ntp * 16 * SA2 + k0) * 2);
                mma16816(acc2[0][2 * ntp],     hw[0] + 4 * ks, b);
                mma16816(acc2[0][2 * ntp + 1], hw[0] + 4 * ks, b + 2);
                mma16816(acc2[1][2 * ntp],     hw[1] + 4 * ks, b);
                mma16816(acc2[1][2 * ntp + 1], hw[1] + 4 * ks, b + 2);
            }
        }

        // ---- epilogue: t' = t*dis, agg2 seed = t*dis^2 ----
        #pragma unroll
        for (int rg = 0; rg < 2; rg++) {
            int rowA = tile * ROWS + r0 + rg * 16 + g, rowB = rowA + 8;
            float dA = g_dis[rowA], dB = g_dis[rowB];
            #pragma unroll
            for (int nt = 0; nt < NT2; nt++) {
                int col = nt * 8 + tg * 2;
                float v0 = acc2[rg][nt][0] * dA, v1 = acc2[rg][nt][1] * dA;
                float v2 = acc2[rg][nt][2] * dB, v3 = acc2[rg][nt][3] * dB;
                *(uint32_t*)(T + (size_t)rowA * N2 + col) = pack_h2(v0, v1);
                *(uint32_t*)(T + (size_t)rowB * N2 + col) = pack_h2(v2, v3);
                *(uint32_t*)(Agg + (size_t)rowA * N2 + col) = pack_h2(v0 * dA, v1 * dA);
                *(uint32_t*)(Agg + (size_t)rowB * N2 + col) = pack_h2(v2 * dB, v3 * dB);
            }
        }
    }
}

// ---------------- vectorized mean pool of relu(agg2 + b2) -------------------
// block = 8 warps; warp w owns 16B chunk q=w (8 features), lanes = 32 node slots.
// Reduction via warp shuffles: race-free, no shared memory.
__global__ void pool_kernel(const float* __restrict__ b2) {
    int b = blockIdx.x / 50, c = blockIdx.x % 50;   // 50 chunks of 1000 nodes
    int tid = threadIdx.x;
    int q = tid >> 5, ni = tid & 31;                // q: 16B chunk, ni: lane/node slot
    int start = c * 1000;
    float bf[8];
    #pragma unroll
    for (int j = 0; j < 8; j++) bf[j] = b2[q * 8 + j];

    float acc[8];
    #pragma unroll
    for (int j = 0; j < 8; j++) acc[j] = 0.0f;

    for (int n = start + ni; n < start + 1000; n += 32) {
        size_t idx = ((size_t)b * NPB + n) * 64 + q * 8;
        uint4 raw = *(const uint4*)(g_agg2 + idx);
        float2 f0 = __half22float2(*(__half2*)&raw.x);
        float2 f1 = __half22float2(*(__half2*)&raw.y);
        float2 f2 = __half22float2(*(__half2*)&raw.z);
        float2 f3 = __half22float2(*(__half2*)&raw.w);
        acc[0] += fmaxf(f0.x + bf[0], 0.0f);
        acc[1] += fmaxf(f0.y + bf[1], 0.0f);
        acc[2] += fmaxf(f1.x + bf[2], 0.0f);
        acc[3] += fmaxf(f1.y + bf[3], 0.0f);
        acc[4] += fmaxf(f2.x + bf[4], 0.0f);
        acc[5] += fmaxf(f2.y + bf[5], 0.0f);
        acc[6] += fmaxf(f3.x + bf[6], 0.0f);
        acc[7] += fmaxf(f3.y + bf[7], 0.0f);
    }

    // butterfly-reduce each feature across the warp's 32 lanes
    #pragma unroll
    for (int j = 0; j < 8; j++) {
        #pragma unroll
        for (int o = 16; o > 0; o >>= 1)
            acc[j] += __shfl_xor_sync(0xffffffffu, acc[j], o);
    }
    if (ni < 8)
        atomicAdd(&g_pooled[b * 64 + q * 8 + ni], acc[ni] * (1.0f / (float)NPB));
}

// ---------------- tiny FC head ---------------------------------------------
__global__ void head_kernel(const float* __restrict__ fc_w,
                            const float* __restrict__ fc_b,
                            const float* __restrict__ out_w,
                            const float* __restrict__ out_b,
                            float* __restrict__ out) {
    __shared__ float P[512], H[512];
    int tid = threadIdx.x;
    P[tid] = g_pooled[tid];
    __syncthreads();
    int b = tid >> 6, j = tid & 63;
    float a = fc_b[j];
    #pragma unroll 8
    for (int k = 0; k < 64; k++) a = fmaf(P[b * 64 + k], fc_w[k * 64 + j], a);
    H[tid] = fmaxf(a, 0.0f);
    __syncthreads();
    float o = out_b[j];
    #pragma unroll 8
    for (int k = 0; k < 64; k++) o = fmaf(H[b * 64 + k], out_w[k * 64 + j], o);
    out[tid] = o;
}

// ---------------- launch ----------------------------------------------------
extern "C" void kernel_launch(void* const* d_in, const int* in_sizes, int n_in,
                              void* d_out, int out_size) {
    const float* x     = (const float*)d_in[0];
    const int*   ei    = (const int*)d_in[1];
    const float* W1    = (const float*)d_in[2];
    const float* b1    = (const float*)d_in[3];
    const float* W2    = (const float*)d_in[4];
    const float* b2    = (const float*)d_in[5];
    const float* fc_w  = (const float*)d_in[6];
    const float* fc_b  = (const float*)d_in[7];
    const float* out_w = (const float*)d_in[8];
    const float* out_b = (const float*)d_in[9];
    float* out = (float*)d_out;

    __half *agg1p, *x16p, *tp, *agg2p;
    int* degp; float* pooledp;
    cudaGetSymbolAddress((void**)&agg1p, g_agg1);
    cudaGetSymbolAddress((void**)&x16p,  g_x16);
    cudaGetSymbolAddress((void**)&tp,    g_t);
    cudaGetSymbolAddress((void**)&agg2p, g_agg2);
    cudaGetSymbolAddress((void**)&degp,  g_deg);
    cudaGetSymbolAddress((void**)&pooledp, g_pooled);

    // smem: A 2*256*72*2 + B1 128*72*2 + B2 64*136*2 + bias 128*4 = 110080
    const int SMEM = 110080;
    cudaFuncSetAttribute(fused_gemm_kernel, cudaFuncAttributeMaxDynamicSharedMemorySize, SMEM);

    cudaMemsetAsync(degp, 0, N_NODES * sizeof(int));
    cudaMemsetAsync(pooledp, 0, 512 * sizeof(float));

    decode_kernel<<<1563, 256>>>(ei);          // (1) indices + degrees
    init_kernel<<<12500, 256>>>(x);            // (2) dis + agg1 seed + x16'

    scatter_kernel<<<12500, 256>>>(x16p, agg1p);           // (3)
    fused_gemm_kernel<<<148, 256, SMEM>>>(agg1p, W1, b1, W2, tp, agg2p, 1563);  // (4) <- profiled
    scatter_kernel<<<12500, 256>>>(tp, agg2p);             // (5)

    pool_kernel<<<400, 256>>>(b2);             // (6)
    head_kernel<<<1, 512>>>(fc_w, fc_b, out_w, out_b, out);  // (7)
}

// round 14
// speedup vs baseline: 1.0336x; 1.0336x over previous
#include <cuda_runtime.h>
#include <cuda_fp16.h>
#include <cstdint>

#define N_NODES 400000
#define N_EDGES 400000
#define NPB 50000

// ---------------- scratch (device globals: no allocation allowed) ----------
__device__ float g_dis[N_NODES];
__device__ int   g_deg[N_NODES];
__device__ int   g_src[N_EDGES];
__device__ int   g_dst[N_EDGES];
__device__ __half g_agg1[(size_t)N_NODES * 64];
__device__ __half g_x16[(size_t)N_NODES * 64];    // x * dis  (pre-scaled)
__device__ __half g_t[(size_t)N_NODES * 64];      // t * dis  (pre-scaled)
__device__ __half g_agg2[(size_t)N_NODES * 64];
__device__ float g_pooled[512];

// ---------------- decode (int32 proven on this dataset) + degree ------------
__global__ void decode_kernel(const int* __restrict__ ei) {
    int e = blockIdx.x * 256 + threadIdx.x;
    if (e >= N_EDGES) return;
    int s = ei[e], d = ei[N_EDGES + e];
    s = min(max(s, 0), N_NODES - 1);    // guard: wrong dtype -> rel_err, not trap
    d = min(max(d, 0), N_NODES - 1);
    g_src[e] = s;
    g_dst[e] = d;
    atomicAdd(&g_deg[d], 1);
}

// ---------------- init: dis + agg1 seed (x*dis^2) + x16 = x*dis -------------
__global__ void init_kernel(const float* __restrict__ x) {
    int gid = blockIdx.x * 256 + threadIdx.x;   // 8 threads/node, 8 floats each
    int i = gid >> 3, q = gid & 7;
    if (i >= N_NODES) return;
    float dv = rsqrtf((float)(g_deg[i] + 1));   // +1 self loop
    if (q == 0) g_dis[i] = dv;
    float dv2 = dv * dv;
    const float4* xp = (const float4*)(x + (size_t)i * 64 + q * 8);
    float4 a = xp[0], b = xp[1];
    uint4 o, s;
    *(__half2*)&o.x = __float22half2_rn(make_float2(a.x * dv, a.y * dv));
    *(__half2*)&o.y = __float22half2_rn(make_float2(a.z * dv, a.w * dv));
    *(__half2*)&o.z = __float22half2_rn(make_float2(b.x * dv, b.y * dv));
    *(__half2*)&o.w = __float22half2_rn(make_float2(b.z * dv, b.w * dv));
    *(__half2*)&s.x = __float22half2_rn(make_float2(a.x * dv2, a.y * dv2));
    *(__half2*)&s.y = __float22half2_rn(make_float2(a.z * dv2, a.w * dv2));
    *(__half2*)&s.z = __float22half2_rn(make_float2(b.x * dv2, b.y * dv2));
    *(__half2*)&s.w = __float22half2_rn(make_float2(b.z * dv2, b.w * dv2));
    ((uint4*)g_x16)[(size_t)i * 8 + q] = o;
    ((uint4*)g_agg1)[(size_t)i * 8 + q] = s;
}

// ---------------- generic edge scatter: out[d] += F[s] * dis[d] --------------
// (F rows are pre-scaled by dis[src])
__device__ __forceinline__ void red_f16x8(__half* p, uint32_t r0, uint32_t r1,
                                          uint32_t r2, uint32_t r3) {
    asm volatile("red.global.add.noftz.v4.f16x2 [%0], {%1,%2,%3,%4};"
                 :: "l"(p), "r"(r0), "r"(r1), "r"(r2), "r"(r3) : "memory");
}

__device__ __forceinline__ uint32_t pack_h2(float a, float b) {
    __half2 h = __float22half2_rn(make_float2(a, b));
    return *(uint32_t*)&h;
}

__global__ void scatter_kernel(const __half* __restrict__ F,
                               __half* __restrict__ out) {
    int gid = blockIdx.x * 256 + threadIdx.x;
    int e = gid >> 3, q = gid & 7;   // 8 threads/edge, 8 fp16 (16B) each
    if (e >= N_EDGES) return;
    int s = g_src[e], d = g_dst[e];
    float w = g_dis[d];
    uint4 raw = ((const uint4*)(F + (size_t)s * 64))[q];
    float2 f0 = __half22float2(*(__half2*)&raw.x);
    float2 f1 = __half22float2(*(__half2*)&raw.y);
    float2 f2 = __half22float2(*(__half2*)&raw.z);
    float2 f3 = __half22float2(*(__half2*)&raw.w);
    red_f16x8(out + (size_t)d * 64 + q * 8,
              pack_h2(f0.x * w, f0.y * w), pack_h2(f1.x * w, f1.y * w),
              pack_h2(f2.x * w, f2.y * w), pack_h2(f3.x * w, f3.y * w));
}

// ---------------- HMMA (f16 accum) + ldmatrix helpers -------------------------
__device__ __forceinline__ void mma16816_h(uint32_t* d, const uint32_t* a,
                                           const uint32_t* b) {
    asm volatile(
        "mma.sync.aligned.m16n8k16.row.col.f16.f16.f16.f16 "
        "{%0,%1}, {%2,%3,%4,%5}, {%6,%7}, {%0,%1};"
        : "+r"(d[0]), "+r"(d[1])
        : "r"(a[0]), "r"(a[1]), "r"(a[2]), "r"(a[3]), "r"(b[0]), "r"(b[1]));
}

__device__ __forceinline__ void ldsm_x4(uint32_t* r, uint32_t addr) {
    asm volatile("ldmatrix.sync.aligned.m8n8.x4.shared.b16 {%0,%1,%2,%3}, [%4];"
                 : "=r"(r[0]), "=r"(r[1]), "=r"(r[2]), "=r"(r[3]) : "r"(addr));
}

__device__ __forceinline__ uint32_t smem_u32(const void* p) {
    uint32_t a;
    asm("{ .reg .u64 t; cvta.to.shared.u64 t, %1; cvt.u32.u64 %0, t; }" : "=r"(a) : "l"(p));
    return a;
}

__device__ __forceinline__ void cp16(uint32_t saddr, const void* g) {
    asm volatile("cp.async.cg.shared.global [%0], [%1], 16;" :: "r"(saddr), "l"(g));
}

__device__ __forceinline__ uint32_t hmul2u(uint32_t a, uint32_t b) {
    __half2 r = __hmul2(*(__half2*)&a, *(__half2*)&b);
    return *(uint32_t*)&r;
}

__device__ __forceinline__ uint32_t hmax2z(uint32_t a) {
    __half2 z = __float2half2_rn(0.0f);
    __half2 r = __hmax2(*(__half2*)&a, z);
    return *(uint32_t*)&r;
}

// ---------------- fused double GEMM (fp16 accumulators) -----------------------
// t' = ( relu(agg1 @ W1 + b1) @ W2 ) * dis ; agg2 seed = t * dis^2.
// fp16 accumulators: D regs = packed half2 in EXACTLY the A-fragment layout of
// the next MMA -> bias folds into C-init, relu is one HMAX2, no packing at all.
// 128-row tiles, 16 rows/warp; ~half the registers of the fp32-accum version.
__global__ void __launch_bounds__(256, 2)
fused_gemm_kernel(const __half* __restrict__ X, const float* __restrict__ W1g,
                  const float* __restrict__ b1, const float* __restrict__ W2g,
                  __half* __restrict__ T, __half* __restrict__ Agg,
                  int tiles) {
    constexpr int K1 = 64, H = 128, N2 = 64;
    constexpr int SA1 = K1 + 8;   // 72
    constexpr int SA2 = H + 8;    // 136
    constexpr int NT1 = H / 8;    // 16
    constexpr int KS1 = K1 / 16;  // 4
    constexpr int NT2 = N2 / 8;   // 8
    constexpr int KS2 = H / 16;   // 8

    extern __shared__ __align__(16) char smraw[];
    __half* A0 = (__half*)smraw;          // 128*SA1
    __half* A1 = A0 + 128 * SA1;
    __half* B1 = A1 + 128 * SA1;          // H*SA1
    __half* B2 = B1 + H * SA1;            // N2*SA2
    uint32_t* sb2 = (uint32_t*)(B2 + N2 * SA2);   // H/2 half2 bias pairs

    int tid = threadIdx.x, wid = tid >> 5, lane = tid & 31;
    int g = lane >> 2, tg = lane & 3, r0 = wid * 16;

    // W1 [K1 x H] -> B1 [n][k] fp16
    for (int e = tid; e < K1 * H; e += 256) {
        int k = e / H, n = e % H;
        B1[n * SA1 + k] = __float2half_rn(W1g[e]);
    }
    // W2 [H x N2] -> B2 [n][k] fp16
    for (int e = tid; e < H * N2; e += 256) {
        int k = e / N2, n = e % N2;
        B2[n * SA2 + k] = __float2half_rn(W2g[e]);
    }
    for (int j = tid; j < H / 2; j += 256)
        sb2[j] = pack_h2(b1[2 * j], b1[2 * j + 1]);

    uint32_t sA[2] = { smem_u32(A0), smem_u32(A1) };
    // A ldmatrix.x4 lane address (16 rows x two 16B k-halves)
    uint32_t a_row = (uint32_t)((lane & 15) + r0) * SA1 * 2 + ((lane >> 4) << 4);
    // B ldmatrix.x4 lane address: 4 matrices = {nt, nt+1} x {k0, k0+8}
    uint32_t bpr = (uint32_t)((lane & 7) + ((lane >> 4) << 3));   // row within pair
    uint32_t bkh = ((lane >> 3) & 1) << 3;                        // k-half offset
    uint32_t b1_addr = smem_u32(B1) + (bpr * SA1 + bkh) * 2;
    uint32_t b2_addr = smem_u32(B2) + (bpr * SA2 + bkh) * 2;

    __syncthreads();
    // per-warp bias fragments: tile nt covers cols nt*8+2tg -> half2 idx nt*4+tg
    uint32_t sbr[NT1];
    #pragma unroll
    for (int nt = 0; nt < NT1; nt++) sbr[nt] = sb2[nt * 4 + tg];

    {   // prologue: prefetch first tile (128 rows x 128B)
        const char* gp = (const char*)(X + (size_t)blockIdx.x * 128 * K1);
        #pragma unroll
        for (int j = 0; j < 4; j++) {
            int idx = tid + j * 256;
            int row = idx >> 3, q = idx & 7;
            cp16(sA[0] + row * (SA1 * 2) + q * 16, gp + row * 128 + q * 16);
        }
        asm volatile("cp.async.commit_group;" ::: "memory");
    }

    int it = 0;
    for (int tile = blockIdx.x; tile < tiles; tile += gridDim.x, it++) {
        __syncthreads();
        int nxt = tile + gridDim.x;
        if (nxt < tiles) {
            const char* gp = (const char*)(X + (size_t)nxt * 128 * K1);
            uint32_t sn = sA[(it + 1) & 1];
            #pragma unroll
            for (int j = 0; j < 4; j++) {
                int idx = tid + j * 256;
                int row = idx >> 3, q = idx & 7;
                cp16(sn + row * (SA1 * 2) + q * 16, gp + row * 128 + q * 16);
            }
            asm volatile("cp.async.commit_group;" ::: "memory");
            asm volatile("cp.async.wait_group 1;" ::: "memory");
        } else {
            asm volatile("cp.async.wait_group 0;" ::: "memory");
        }
        __syncthreads();

        uint32_t aBase = sA[it & 1] + a_row;

        // ---- stage 1: acc1 = bias + A @ W1 (fp16 accum; bias = C init) ----
        uint32_t acc1[NT1][2];
        #pragma unroll
        for (int nt = 0; nt < NT1; nt++) {
            acc1[nt][0] = sbr[nt];   // rows g   : cols (2tg, 2tg+1) of tile nt
            acc1[nt][1] = sbr[nt];   // rows g+8 : same cols
        }

        #pragma unroll
        for (int ks = 0; ks < KS1; ks++) {
            int k0 = ks * 16;
            uint32_t a[4];
            ldsm_x4(a, aBase + k0 * 2);
            #pragma unroll
            for (int ntp = 0; ntp < NT1 / 2; ntp++) {
                uint32_t b[4];
                ldsm_x4(b, b1_addr + (ntp * 16 * SA1 + k0) * 2);
                mma16816_h(acc1[2 * ntp],     a, b);
                mma16816_h(acc1[2 * ntp + 1], a, b + 2);
            }
        }

        // ---- relu in place: acc1 IS the stage-2 A fragment set ----
        #pragma unroll
        for (int nt = 0; nt < NT1; nt++) {
            acc1[nt][0] = hmax2z(acc1[nt][0]);
            acc1[nt][1] = hmax2z(acc1[nt][1]);
        }

        // ---- stage 2: acc2 = h @ W2 (fp16 accum), h straight from acc1 ----
        uint32_t acc2[NT2][2];
        #pragma unroll
        for (int nt = 0; nt < NT2; nt++) { acc2[nt][0] = 0u; acc2[nt][1] = 0u; }

        #pragma unroll
        for (int ks = 0; ks < KS2; ks++) {
            int k0 = ks * 16;
            uint32_t a[4];
            a[0] = acc1[2 * ks][0];       // [g][k0+2tg]
            a[1] = acc1[2 * ks][1];       // [g+8][k0+2tg]
            a[2] = acc1[2 * ks + 1][0];   // [g][k0+8+2tg]
            a[3] = acc1[2 * ks + 1][1];   // [g+8][k0+8+2tg]
            #pragma unroll
            for (int ntp = 0; ntp < NT2 / 2; ntp++) {
                uint32_t b[4];
                ldsm_x4(b, b2_addr + (ntp * 16 * SA2 + k0) * 2);
                mma16816_h(acc2[2 * ntp],     a, b);
                mma16816_h(acc2[2 * ntp + 1], a, b + 2);
            }
        }

        // ---- epilogue: t' = t*dis, agg2 seed = t*dis^2 (all half2 muls) ----
        int rowA = tile * 128 + r0 + g, rowB = rowA + 8;
        uint32_t dA2, dB2;
        { __half2 h = __float2half2_rn(g_dis[rowA]); dA2 = *(uint32_t*)&h; }
        { __half2 h = __float2half2_rn(g_dis[rowB]); dB2 = *(uint32_t*)&h; }
        #pragma unroll
        for (int nt = 0; nt < NT2; nt++) {
            int col = nt * 8 + tg * 2;
            uint32_t t0 = hmul2u(acc2[nt][0], dA2);
            uint32_t t1 = hmul2u(acc2[nt][1], dB2);
            *(uint32_t*)(T + (size_t)rowA * N2 + col) = t0;
            *(uint32_t*)(T + (size_t)rowB * N2 + col) = t1;
            *(uint32_t*)(Agg + (size_t)rowA * N2 + col) = hmul2u(t0, dA2);
            *(uint32_t*)(Agg + (size_t)rowB * N2 + col) = hmul2u(t1, dB2);
        }
    }
}

// ---------------- vectorized mean pool of relu(agg2 + b2) -------------------
// block = 8 warps; warp w owns 16B chunk q=w (8 features), lanes = 32 node slots.
// Reduction via warp shuffles: race-free, no shared memory.
__global__ void pool_kernel(const float* __restrict__ b2) {
    int b = blockIdx.x / 50, c = blockIdx.x % 50;   // 50 chunks of 1000 nodes
    int tid = threadIdx.x;
    int q = tid >> 5, ni = tid & 31;                // q: 16B chunk, ni: lane/node slot
    int start = c * 1000;
    float bf[8];
    #pragma unroll
    for (int j = 0; j < 8; j++) bf[j] = b2[q * 8 + j];

    float acc[8];
    #pragma unroll
    for (int j = 0; j < 8; j++) acc[j] = 0.0f;

    for (int n = start + ni; n < start + 1000; n += 32) {
        size_t idx = ((size_t)b * NPB + n) * 64 + q * 8;
        uint4 raw = *(const uint4*)(g_agg2 + idx);
        float2 f0 = __half22float2(*(__half2*)&raw.x);
        float2 f1 = __half22float2(*(__half2*)&raw.y);
        float2 f2 = __half22float2(*(__half2*)&raw.z);
        float2 f3 = __half22float2(*(__half2*)&raw.w);
        acc[0] += fmaxf(f0.x + bf[0], 0.0f);
        acc[1] += fmaxf(f0.y + bf[1], 0.0f);
        acc[2] += fmaxf(f1.x + bf[2], 0.0f);
        acc[3] += fmaxf(f1.y + bf[3], 0.0f);
        acc[4] += fmaxf(f2.x + bf[4], 0.0f);
        acc[5] += fmaxf(f2.y + bf[5], 0.0f);
        acc[6] += fmaxf(f3.x + bf[6], 0.0f);
        acc[7] += fmaxf(f3.y + bf[7], 0.0f);
    }

    // butterfly-reduce each feature across the warp's 32 lanes
    #pragma unroll
    for (int j = 0; j < 8; j++) {
        #pragma unroll
        for (int o = 16; o > 0; o >>= 1)
            acc[j] += __shfl_xor_sync(0xffffffffu, acc[j], o);
    }
    if (ni < 8)
        atomicAdd(&g_pooled[b * 64 + q * 8 + ni], acc[ni] * (1.0f / (float)NPB));
}

// ---------------- tiny FC head ---------------------------------------------
__global__ void head_kernel(const float* __restrict__ fc_w,
                            const float* __restrict__ fc_b,
                            const float* __restrict__ out_w,
                            const float* __restrict__ out_b,
                            float* __restrict__ out) {
    __shared__ float P[512], H[512];
    int tid = threadIdx.x;
    P[tid] = g_pooled[tid];
    __syncthreads();
    int b = tid >> 6, j = tid & 63;
    float a = fc_b[j];
    #pragma unroll 8
    for (int k = 0; k < 64; k++) a = fmaf(P[b * 64 + k], fc_w[k * 64 + j], a);
    H[tid] = fmaxf(a, 0.0f);
    __syncthreads();
    float o = out_b[j];
    #pragma unroll 8
    for (int k = 0; k < 64; k++) o = fmaf(H[b * 64 + k], out_w[k * 64 + j], o);
    out[tid] = o;
}

// ---------------- launch ----------------------------------------------------
extern "C" void kernel_launch(void* const* d_in, const int* in_sizes, int n_in,
                              void* d_out, int out_size) {
    const float* x     = (const float*)d_in[0];
    const int*   ei    = (const int*)d_in[1];
    const float* W1    = (const float*)d_in[2];
    const float* b1    = (const float*)d_in[3];
    const float* W2    = (const float*)d_in[4];
    const float* b2    = (const float*)d_in[5];
    const float* fc_w  = (const float*)d_in[6];
    const float* fc_b  = (const float*)d_in[7];
    const float* out_w = (const float*)d_in[8];
    const float* out_b = (const float*)d_in[9];
    float* out = (float*)d_out;

    __half *agg1p, *x16p, *tp, *agg2p;
    int* degp; float* pooledp;
    cudaGetSymbolAddress((void**)&agg1p, g_agg1);
    cudaGetSymbolAddress((void**)&x16p,  g_x16);
    cudaGetSymbolAddress((void**)&tp,    g_t);
    cudaGetSymbolAddress((void**)&agg2p, g_agg2);
    cudaGetSymbolAddress((void**)&degp,  g_deg);
    cudaGetSymbolAddress((void**)&pooledp, g_pooled);

    // smem: A 2*128*72*2 + B1 128*72*2 + B2 64*136*2 + sb2 64*4 = 73216
    const int SMEM = 73216;
    cudaFuncSetAttribute(fused_gemm_kernel, cudaFuncAttributeMaxDynamicSharedMemorySize, SMEM);

    cudaMemsetAsync(degp, 0, N_NODES * sizeof(int));
    cudaMemsetAsync(pooledp, 0, 512 * sizeof(float));

    decode_kernel<<<1563, 256>>>(ei);          // (1) indices + degrees
    init_kernel<<<12500, 256>>>(x);            // (2) dis + agg1 seed + x16'

    scatter_kernel<<<12500, 256>>>(x16p, agg1p);           // (3)
    fused_gemm_kernel<<<296, 256, SMEM>>>(agg1p, W1, b1, W2, tp, agg2p, 3125);  // (4) <- profiled
    scatter_kernel<<<12500, 256>>>(tp, agg2p);             // (5)

    pool_kernel<<<400, 256>>>(b2);             // (6)
    head_kernel<<<1, 512>>>(fc_w, fc_b, out_w, out_b, out);  // (7)
}